// round 15
// baseline (speedup 1.0000x reference)
#include <cuda_runtime.h>
#include <cstdint>

#define BATCH 64
#define TDIM  2048
#define QDIM  512
#define KDIM  512

// Block-role layout in the fused grid
#define MIDS_BLOCKS   256                    // kt(16, 32 k each) x bt(16, 4 b each)
#define SCORE_BLOCKS  2048                   // b(64) x chunk(32), 64 rows each
#define NORM_BLOCKS   128                    // 2 per batch
#define TOTAL_BLOCKS  (MIDS_BLOCKS + SCORE_BLOCKS + NORM_BLOCKS)

// Scratch (no allocations allowed in kernel_launch). All counters start 0
// (static init) and are reset to 0 by the end of every launch (replay-safe).
__device__ float g_mids[BATCH * KDIM];
__device__ float g_sums[BATCH];          // reset by norm tail
__device__ int   g_mids_cnt[16];         // per-bt mids completion (target 16)
__device__ int   g_mids_passed[16];      // per-bt scores passers (target 128)
__device__ int   g_sc_cnt[BATCH];        // per-batch scores completion (target 32)
__device__ int   g_sc_passed[BATCH];     // per-batch norm passers (target 2)

// Scoped release/acquire: orders prior writes at GPU scope WITHOUT the full
// MEMBAR.GPU store-drain of __threadfence().
__device__ __forceinline__ int ld_acquire(const int* p) {
    int v;
    asm volatile("ld.acquire.gpu.global.s32 %0, [%1];" : "=r"(v) : "l"(p) : "memory");
    return v;
}
__device__ __forceinline__ void red_release_add(int* p, int v) {
    asm volatile("red.release.gpu.global.add.s32 [%0], %1;" :: "l"(p), "r"(v) : "memory");
}
__device__ __forceinline__ void spin_acquire(const int* p, int target) {
    while (ld_acquire(p) < target) __nanosleep(64);
}

__global__ void __launch_bounds__(256)
fused_kernel(const float* __restrict__ query,
             const float* __restrict__ key,
             const float* __restrict__ W,
             const float* __restrict__ bias,
             float* __restrict__ out)
{
    // Shared pool: mids role uses 8192 floats (q_s); scores uses 512 (ms).
    __shared__ __align__(16) float sh[8192];
    __shared__ float blockSum;

    const int bid  = blockIdx.x;
    const int tid  = threadIdx.x;
    const int warp = tid >> 5;
    const int lane = tid & 31;

    // ======================= ROLE 1: mids =======================
    if (bid < MIDS_BLOCKS) {
        const int kt = bid & 15;   // 0..15 (32 k each)
        const int bt = bid >> 4;   // 0..15 (4 b each)

        float (*q_s)[QDIM] = reinterpret_cast<float(*)[QDIM]>(sh);
        {
            const float4* qg = reinterpret_cast<const float4*>(
                query + (size_t)bt * 4 * QDIM);
            float4* qs4 = reinterpret_cast<float4*>(sh);
            qs4[tid]       = qg[tid];
            qs4[tid + 256] = qg[tid + 256];
        }
        __syncthreads();

        // Each warp owns 4 k's, processed as 2 sequential pairs.
#pragma unroll
        for (int pair = 0; pair < 2; pair++) {
            const int k0 = kt * 32 + warp * 4 + pair * 2;
            const float4* w4a = reinterpret_cast<const float4*>(
                W + (size_t)k0 * QDIM);
            const float4* w4b = w4a + QDIM / 4;   // row k0+1

            float a[2][4] = {};
#pragma unroll
            for (int j = 0; j < 4; j++) {
                const int idx = lane + 32 * j;
                const float4 w0 = w4a[idx];   // W streamed (used once)
                const float4 w1 = w4b[idx];
#pragma unroll
                for (int bb = 0; bb < 4; bb++) {
                    const float4 v = reinterpret_cast<const float4*>(q_s[bb])[idx];
                    a[0][bb] += w0.x * v.x + w0.y * v.y + w0.z * v.z + w0.w * v.w;
                    a[1][bb] += w1.x * v.x + w1.y * v.y + w1.z * v.z + w1.w * v.w;
                }
            }
#pragma unroll
            for (int o = 16; o; o >>= 1) {
#pragma unroll
                for (int bb = 0; bb < 4; bb++) {
                    a[0][bb] += __shfl_xor_sync(0xffffffffu, a[0][bb], o);
                    a[1][bb] += __shfl_xor_sync(0xffffffffu, a[1][bb], o);
                }
            }
            if (lane == 0) {
#pragma unroll
                for (int bb = 0; bb < 4; bb++) {
                    const int b = bt * 4 + bb;
                    g_mids[(size_t)b * KDIM + k0]     = a[0][bb];
                    g_mids[(size_t)b * KDIM + k0 + 1] = a[1][bb];
                }
            }
        }
        __syncthreads();
        if (tid == 0) red_release_add(&g_mids_cnt[bt], 1);   // publish g_mids
        return;
    }

    // ======================= ROLE 2: scores =======================
    if (bid < MIDS_BLOCKS + SCORE_BLOCKS) {
        const int sid   = bid - MIDS_BLOCKS;
        const int b     = sid >> 5;   // 0..63
        const int chunk = sid & 31;   // 0..31 (64 rows each)
        const int bt    = b >> 2;

        const float4* tb4 = reinterpret_cast<const float4*>(
            key + ((size_t)b * TDIM + chunk * 64) * KDIM);

        // ---- L2-prefetch the whole 128KB tile BEFORE waiting on mids.
        // Fire-and-forget: zero register/smem footprint; ramp-phase blocks
        // convert their spin time into DRAM->L2 streaming, steady-state
        // blocks get L2-hit latency (~234cyc) in the hot loop. ----
        {
            const char* tbc = reinterpret_cast<const char*>(tb4);
#pragma unroll
            for (int r = 0; r < 4; r++) {
                asm volatile("prefetch.global.L2 [%0];"
                             :: "l"(tbc + (size_t)(tid + 256 * r) * 128));
            }
        }

        if (tid == 0) {
            blockSum = 0.0f;
            spin_acquire(g_mids_cnt + bt, 16);   // wait for this batch's mids
            int p = atomicAdd(&g_mids_passed[bt], 1);
            if (p == 127) { g_mids_cnt[bt] = 0; g_mids_passed[bt] = 0; }
        }
        __syncthreads();                          // mids visible to all

        if (tid < KDIM / 4) {
            reinterpret_cast<float4*>(sh)[tid] =
                reinterpret_cast<const float4*>(g_mids + (size_t)b * KDIM)[tid];
        }
        __syncthreads();                          // ms ready

        float4 m[4];
#pragma unroll
        for (int j = 0; j < 4; j++)
            m[j] = reinterpret_cast<const float4*>(sh)[lane + 32 * j];

        const float4* kb = tb4 + warp * 8 * 128;  // tile rows w*8..w*8+7

        float a0 = 0.f, a1 = 0.f, a2 = 0.f, a3 = 0.f;
        float a4 = 0.f, a5 = 0.f, a6 = 0.f, a7 = 0.f;
#pragma unroll
        for (int j = 0; j < 4; j++) {
            const int idx = lane + 32 * j;
            const float4 mv = m[j];
            float4 v0 = __ldcs(kb + idx + 0 * 128);
            float4 v1 = __ldcs(kb + idx + 1 * 128);
            float4 v2 = __ldcs(kb + idx + 2 * 128);
            float4 v3 = __ldcs(kb + idx + 3 * 128);
            float4 v4 = __ldcs(kb + idx + 4 * 128);
            float4 v5 = __ldcs(kb + idx + 5 * 128);
            float4 v6 = __ldcs(kb + idx + 6 * 128);
            float4 v7 = __ldcs(kb + idx + 7 * 128);
            a0 += v0.x * mv.x + v0.y * mv.y + v0.z * mv.z + v0.w * mv.w;
            a1 += v1.x * mv.x + v1.y * mv.y + v1.z * mv.z + v1.w * mv.w;
            a2 += v2.x * mv.x + v2.y * mv.y + v2.z * mv.z + v2.w * mv.w;
            a3 += v3.x * mv.x + v3.y * mv.y + v3.z * mv.z + v3.w * mv.w;
            a4 += v4.x * mv.x + v4.y * mv.y + v4.z * mv.z + v4.w * mv.w;
            a5 += v5.x * mv.x + v5.y * mv.y + v5.z * mv.z + v5.w * mv.w;
            a6 += v6.x * mv.x + v6.y * mv.y + v6.z * mv.z + v6.w * mv.w;
            a7 += v7.x * mv.x + v7.y * mv.y + v7.z * mv.z + v7.w * mv.w;
        }
#pragma unroll
        for (int o = 16; o; o >>= 1) {
            a0 += __shfl_xor_sync(0xffffffffu, a0, o);
            a1 += __shfl_xor_sync(0xffffffffu, a1, o);
            a2 += __shfl_xor_sync(0xffffffffu, a2, o);
            a3 += __shfl_xor_sync(0xffffffffu, a3, o);
            a4 += __shfl_xor_sync(0xffffffffu, a4, o);
            a5 += __shfl_xor_sync(0xffffffffu, a5, o);
            a6 += __shfl_xor_sync(0xffffffffu, a6, o);
            a7 += __shfl_xor_sync(0xffffffffu, a7, o);
        }

        if (lane == 0) {
            const float bv = bias[0];
            float4 e0, e1;
            e0.x = __expf(tanhf(a0 + bv));
            e0.y = __expf(tanhf(a1 + bv));
            e0.z = __expf(tanhf(a2 + bv));
            e0.w = __expf(tanhf(a3 + bv));
            e1.x = __expf(tanhf(a4 + bv));
            e1.y = __expf(tanhf(a5 + bv));
            e1.z = __expf(tanhf(a6 + bv));
            e1.w = __expf(tanhf(a7 + bv));
            const int ta = chunk * 64 + warp * 8;
            float4* op = reinterpret_cast<float4*>(out + (size_t)b * TDIM + ta);
            op[0] = e0;
            op[1] = e1;
            atomicAdd(&blockSum,
                      ((e0.x + e0.y) + (e0.z + e0.w)) +
                      ((e1.x + e1.y) + (e1.z + e1.w)));
        }
        __syncthreads();
        if (tid == 0) {
            atomicAdd(&g_sums[b], blockSum);
            red_release_add(&g_sc_cnt[b], 1);   // release: orders out + sum
        }
        return;
    }

    // ======================= ROLE 3: norm =======================
    {
        const int nid  = bid - MIDS_BLOCKS - SCORE_BLOCKS;  // 0..127
        const int b    = nid >> 1;
        const int half = nid & 1;

        if (tid == 0) {
            spin_acquire(g_sc_cnt + b, 32);  // all 32 scores blocks of b done
        }
        __syncthreads();

        const float inv = 1.0f / __ldcg(&g_sums[b]);
        float4* o4 = reinterpret_cast<float4*>(out + (size_t)b * TDIM);
        const int i = half * 256 + tid;      // 512 float4 per batch
        float4 v = __ldcg(&o4[i]);
        v.x *= inv; v.y *= inv; v.z *= inv; v.w *= inv;
        o4[i] = v;

        __syncthreads();
        if (tid == 0) {
            int p = atomicAdd(&g_sc_passed[b], 1);
            if (p == 1) {
                g_sc_cnt[b]    = 0;
                g_sc_passed[b] = 0;
                g_sums[b]      = 0.0f;
            }
        }
    }
}

// ---------------------------------------------------------------------------
// Inputs (metadata order): query [64,512], key [64,2048,512], W [512,512],
// bias [1]. Output: [64,2048] float32.
// ---------------------------------------------------------------------------
extern "C" void kernel_launch(void* const* d_in, const int* in_sizes, int n_in,
                              void* d_out, int out_size)
{
    const float* query = (const float*)d_in[0];
    const float* key   = (const float*)d_in[1];
    const float* W     = (const float*)d_in[2];
    const float* bias  = (const float*)d_in[3];
    float* out = (float*)d_out;

    fused_kernel<<<TOTAL_BLOCKS, 256>>>(query, key, W, bias, out);
}

// round 16
// speedup vs baseline: 1.1342x; 1.1342x over previous
#include <cuda_runtime.h>
#include <cstdint>

#define BATCH 64
#define TDIM  2048
#define QDIM  512
#define KDIM  512

#define SCORE_BLOCKS  2048                   // b(64) x chunk(32), 64 rows each
#define MIDS_DUTIES   256                    // kt(16, 32 k each) x bt(16, 4 b each)
#define PRE_ROWS      16                     // prefetched rows per scores block

// Scratch (no allocations allowed in kernel_launch). All counters start 0
// (static init) and are reset by end of each launch (replay-safe).
__device__ float g_mids[BATCH * KDIM];
__device__ float g_sums[BATCH];          // reset by the norm epilogue
__device__ int   g_mids_cnt[16];         // per-bt mids completion (target 16)
__device__ int   g_mids_passed[16];      // per-bt scores passers (target 128)
__device__ int   g_sc_cnt[BATCH];        // per-batch scores completion (target 32)

// Scoped release/acquire (no full MEMBAR.GPU store-drain).
__device__ __forceinline__ int ld_acquire(const int* p) {
    int v;
    asm volatile("ld.acquire.gpu.global.s32 %0, [%1];" : "=r"(v) : "l"(p) : "memory");
    return v;
}
__device__ __forceinline__ void red_release_add(int* p, int v) {
    asm volatile("red.release.gpu.global.add.s32 [%0], %1;" :: "l"(p), "r"(v) : "memory");
}
__device__ __forceinline__ int atom_acqrel_add(int* p, int v) {
    int old;
    asm volatile("atom.acq_rel.gpu.global.add.s32 %0, [%1], %2;"
                 : "=r"(old) : "l"(p), "r"(v) : "memory");
    return old;
}
__device__ __forceinline__ void spin_acquire(const int* p, int target) {
    while (ld_acquire(p) < target) __nanosleep(64);
}
__device__ __forceinline__ void cp16(uint32_t saddr, const void* gaddr) {
    asm volatile("cp.async.cg.shared.global [%0], [%1], 16;"
                 :: "r"(saddr), "l"(gaddr) : "memory");
}

// smem layout (floats): [0,512) ms | [512, 512+8192) key tile | [8704, 10752) q_s
#define SH_TILE 512
#define SH_QS   (512 + PRE_ROWS * KDIM)
#define SH_SIZE (SH_QS + 4 * QDIM)

__global__ void __launch_bounds__(256)
fused_kernel(const float* __restrict__ query,
             const float* __restrict__ key,
             const float* __restrict__ W,
             const float* __restrict__ bias,
             float* __restrict__ out)
{
    __shared__ __align__(16) float sh[SH_SIZE];
    __shared__ float blockSum;

    const int sid  = blockIdx.x;
    const int tid  = threadIdx.x;
    const int warp = tid >> 5;
    const int lane = tid & 31;

    const int b     = sid >> 5;   // 0..63
    const int chunk = sid & 31;   // 0..31 (64 rows each)
    const int bt    = b >> 2;

    const float4* tb4 = reinterpret_cast<const float4*>(
        key + ((size_t)b * TDIM + chunk * 64) * KDIM);

    // ---- 1) prefetch rows {w*8+0, w*8+1 : w in 0..7} of own tile into smem
    //         (fills DRAM during mids duty / spin) ----
    const uint32_t ks_base = (uint32_t)__cvta_generic_to_shared(sh + SH_TILE);
#pragma unroll
    for (int r = 0; r < (PRE_ROWS * KDIM / 4) / 256; r++) {
        const int idx = tid + 256 * r;        // 0..2047 float4 slots
        const int s   = idx >> 7;             // smem row slot 0..15
        const int c   = idx & 127;            // float4 column
        const int g   = ((s >> 1) << 3) + (s & 1);  // tile row
        cp16(ks_base + (uint32_t)idx * 16, tb4 + g * 128 + c);
    }
    asm volatile("cp.async.commit_group;" ::: "memory");

    // ---- 2) mids duty (blocks 0..255 only; all wave-1 resident) ----
    if (sid < MIDS_DUTIES) {
        const int dkt = sid & 15;   // 0..15 (32 k each)
        const int dbt = sid >> 4;   // 0..15 (4 b each)

        float (*q_s)[QDIM] = reinterpret_cast<float(*)[QDIM]>(sh + SH_QS);
        {
            const float4* qg = reinterpret_cast<const float4*>(
                query + (size_t)dbt * 4 * QDIM);
            float4* qs4 = reinterpret_cast<float4*>(sh + SH_QS);
            qs4[tid]       = qg[tid];
            qs4[tid + 256] = qg[tid + 256];
        }
        __syncthreads();

#pragma unroll
        for (int pair = 0; pair < 2; pair++) {
            const int k0 = dkt * 32 + warp * 4 + pair * 2;
            const float4* w4a = reinterpret_cast<const float4*>(
                W + (size_t)k0 * QDIM);
            const float4* w4b = w4a + QDIM / 4;

            float a[2][4] = {};
#pragma unroll
            for (int j = 0; j < 4; j++) {
                const int idx = lane + 32 * j;
                const float4 w0 = w4a[idx];
                const float4 w1 = w4b[idx];
#pragma unroll
                for (int bb = 0; bb < 4; bb++) {
                    const float4 v = reinterpret_cast<const float4*>(q_s[bb])[idx];
                    a[0][bb] += w0.x * v.x + w0.y * v.y + w0.z * v.z + w0.w * v.w;
                    a[1][bb] += w1.x * v.x + w1.y * v.y + w1.z * v.z + w1.w * v.w;
                }
            }
#pragma unroll
            for (int o = 16; o; o >>= 1) {
#pragma unroll
                for (int bb = 0; bb < 4; bb++) {
                    a[0][bb] += __shfl_xor_sync(0xffffffffu, a[0][bb], o);
                    a[1][bb] += __shfl_xor_sync(0xffffffffu, a[1][bb], o);
                }
            }
            if (lane == 0) {
#pragma unroll
                for (int bb = 0; bb < 4; bb++) {
                    const int db = dbt * 4 + bb;
                    g_mids[(size_t)db * KDIM + k0]     = a[0][bb];
                    g_mids[(size_t)db * KDIM + k0 + 1] = a[1][bb];
                }
            }
        }
        __syncthreads();
        if (tid == 0) red_release_add(&g_mids_cnt[dbt], 1);   // publish
    }

    // ---- 3) wait for this batch's mids ----
    if (tid == 0) {
        blockSum = 0.0f;
        spin_acquire(g_mids_cnt + bt, 16);
        int p = atomicAdd(&g_mids_passed[bt], 1);
        if (p == 127) { g_mids_cnt[bt] = 0; g_mids_passed[bt] = 0; }
    }
    __syncthreads();

    if (tid < KDIM / 4) {
        reinterpret_cast<float4*>(sh)[tid] =
            reinterpret_cast<const float4*>(g_mids + (size_t)b * KDIM)[tid];
    }
    asm volatile("cp.async.wait_group 0;" ::: "memory");
    __syncthreads();                          // ms + tile ready

    // ---- 4) scores hot loop (R11/R14 proven structure) ----
    float4 m[4];
#pragma unroll
    for (int j = 0; j < 4; j++)
        m[j] = reinterpret_cast<const float4*>(sh)[lane + 32 * j];

    const float4* ks4 = reinterpret_cast<const float4*>(sh + SH_TILE);
    const float4* s0  = ks4 + (warp * 2) * 128;      // row w*8+0
    const float4* s1  = s0 + 128;                    // row w*8+1
    const float4* kb  = tb4 + warp * 8 * 128;        // tile rows w*8..

    float a0 = 0.f, a1 = 0.f, a2 = 0.f, a3 = 0.f;
    float a4 = 0.f, a5 = 0.f, a6 = 0.f, a7 = 0.f;
#pragma unroll
    for (int j = 0; j < 4; j++) {
        const int idx = lane + 32 * j;
        const float4 mv = m[j];
        float4 v0 = s0[idx];                 // smem (prefetched)
        float4 v1 = s1[idx];                 // smem (prefetched)
        float4 v2 = __ldcs(kb + idx + 2 * 128);
        float4 v3 = __ldcs(kb + idx + 3 * 128);
        float4 v4 = __ldcs(kb + idx + 4 * 128);
        float4 v5 = __ldcs(kb + idx + 5 * 128);
        float4 v6 = __ldcs(kb + idx + 6 * 128);
        float4 v7 = __ldcs(kb + idx + 7 * 128);
        a0 += v0.x * mv.x + v0.y * mv.y + v0.z * mv.z + v0.w * mv.w;
        a1 += v1.x * mv.x + v1.y * mv.y + v1.z * mv.z + v1.w * mv.w;
        a2 += v2.x * mv.x + v2.y * mv.y + v2.z * mv.z + v2.w * mv.w;
        a3 += v3.x * mv.x + v3.y * mv.y + v3.z * mv.z + v3.w * mv.w;
        a4 += v4.x * mv.x + v4.y * mv.y + v4.z * mv.z + v4.w * mv.w;
        a5 += v5.x * mv.x + v5.y * mv.y + v5.z * mv.z + v5.w * mv.w;
        a6 += v6.x * mv.x + v6.y * mv.y + v6.z * mv.z + v6.w * mv.w;
        a7 += v7.x * mv.x + v7.y * mv.y + v7.z * mv.z + v7.w * mv.w;
    }
#pragma unroll
    for (int o = 16; o; o >>= 1) {
        a0 += __shfl_xor_sync(0xffffffffu, a0, o);
        a1 += __shfl_xor_sync(0xffffffffu, a1, o);
        a2 += __shfl_xor_sync(0xffffffffu, a2, o);
        a3 += __shfl_xor_sync(0xffffffffu, a3, o);
        a4 += __shfl_xor_sync(0xffffffffu, a4, o);
        a5 += __shfl_xor_sync(0xffffffffu, a5, o);
        a6 += __shfl_xor_sync(0xffffffffu, a6, o);
        a7 += __shfl_xor_sync(0xffffffffu, a7, o);
    }

    if (lane == 0) {
        const float bv = bias[0];
        float4 e0, e1;
        e0.x = __expf(tanhf(a0 + bv));
        e0.y = __expf(tanhf(a1 + bv));
        e0.z = __expf(tanhf(a2 + bv));
        e0.w = __expf(tanhf(a3 + bv));
        e1.x = __expf(tanhf(a4 + bv));
        e1.y = __expf(tanhf(a5 + bv));
        e1.z = __expf(tanhf(a6 + bv));
        e1.w = __expf(tanhf(a7 + bv));
        const int ta = chunk * 64 + warp * 8;
        float4* op = reinterpret_cast<float4*>(out + (size_t)b * TDIM + ta);
        op[0] = e0;
        op[1] = e1;
        atomicAdd(&blockSum,
                  ((e0.x + e0.y) + (e0.z + e0.w)) +
                  ((e1.x + e1.y) + (e1.z + e1.w)));
    }
    __syncthreads();

    // ---- 5) epilogue: last block of each batch normalizes in place ----
    __shared__ int amLast;
    if (tid == 0) {
        atomicAdd(&g_sums[b], blockSum);
        // acq_rel: releases our out-stores+sum; acquires all others' if last
        amLast = (atom_acqrel_add(&g_sc_cnt[b], 1) == 31);
    }
    __syncthreads();

    if (amLast) {
        const float inv = 1.0f / __ldcg(&g_sums[b]);
        float4* o4 = reinterpret_cast<float4*>(out + (size_t)b * TDIM);
#pragma unroll
        for (int r = 0; r < 2; r++) {
            const int i = tid + r * 256;     // 512 float4 per batch
            float4 v = __ldcg(&o4[i]);
            v.x *= inv; v.y *= inv; v.z *= inv; v.w *= inv;
            o4[i] = v;
        }
        __syncthreads();
        if (tid == 0) {                      // reset for graph replay
            g_sc_cnt[b] = 0;
            g_sums[b]   = 0.0f;
        }
    }
}

// ---------------------------------------------------------------------------
// Inputs (metadata order): query [64,512], key [64,2048,512], W [512,512],
// bias [1]. Output: [64,2048] float32.
// ---------------------------------------------------------------------------
extern "C" void kernel_launch(void* const* d_in, const int* in_sizes, int n_in,
                              void* d_out, int out_size)
{
    const float* query = (const float*)d_in[0];
    const float* key   = (const float*)d_in[1];
    const float* W     = (const float*)d_in[2];
    const float* bias  = (const float*)d_in[3];
    float* out = (float*)d_out;

    fused_kernel<<<SCORE_BLOCKS, 256>>>(query, key, W, bias, out);
}

// round 17
// speedup vs baseline: 1.1701x; 1.0316x over previous
#include <cuda_runtime.h>
#include <cstdint>

#define BATCH 64
#define TDIM  2048
#define QDIM  512
#define KDIM  512

#define SCORE_BLOCKS  2048                   // b(64) x chunk(32), 64 rows each
#define MIDS_DUTIES   256                    // kt(16, 32 k each) x bt(16, 4 b each)
#define PRE_ROWS      16                     // prefetched rows per scores block

// Scratch (no allocations allowed in kernel_launch). All counters start 0
// (static init) and are reset by end of each launch (replay-safe).
__device__ float g_mids[BATCH * KDIM];
__device__ float g_sums[BATCH];          // reset by the norm epilogue
__device__ int   g_mids_cnt[16];         // per-bt mids completion (target 16)
__device__ int   g_mids_passed[16];      // per-bt scores passers (target 128)
__device__ int   g_sc_cnt[BATCH];        // per-batch scores completion (target 32)

// Scoped release/acquire (no full MEMBAR.GPU store-drain).
__device__ __forceinline__ int ld_acquire(const int* p) {
    int v;
    asm volatile("ld.acquire.gpu.global.s32 %0, [%1];" : "=r"(v) : "l"(p) : "memory");
    return v;
}
__device__ __forceinline__ void red_release_add(int* p, int v) {
    asm volatile("red.release.gpu.global.add.s32 [%0], %1;" :: "l"(p), "r"(v) : "memory");
}
__device__ __forceinline__ int atom_acqrel_add(int* p, int v) {
    int old;
    asm volatile("atom.acq_rel.gpu.global.add.s32 %0, [%1], %2;"
                 : "=r"(old) : "l"(p), "r"(v) : "memory");
    return old;
}
__device__ __forceinline__ void spin_acquire(const int* p, int target) {
    while (ld_acquire(p) < target) __nanosleep(64);
}
__device__ __forceinline__ void cp16(uint32_t saddr, const void* gaddr) {
    asm volatile("cp.async.cg.shared.global [%0], [%1], 16;"
                 :: "r"(saddr), "l"(gaddr) : "memory");
}

// smem layout (floats):
//   [0, 8192)            key tile (16 rows x 512)
//   [8192, 8192+2048)    q_s (mids duty, phases 1-2) -- REUSED as:
//   [8192, 8192+512)     ms (scores, phase 3+)       -- q_s dead by then
#define SH_TILE 0
#define SH_QS   (PRE_ROWS * KDIM)            // 8192
#define SH_MS   SH_QS                        // overlays q_s (dead after duty)
#define SH_SIZE (SH_QS + 4 * QDIM)           // 10240 floats = 40 KB

__global__ void __launch_bounds__(256, 4)
fused_kernel(const float* __restrict__ query,
             const float* __restrict__ key,
             const float* __restrict__ W,
             const float* __restrict__ bias,
             float* __restrict__ out)
{
    __shared__ __align__(16) float sh[SH_SIZE];
    __shared__ float blockSum;

    const int sid  = blockIdx.x;
    const int tid  = threadIdx.x;
    const int warp = tid >> 5;
    const int lane = tid & 31;

    const int b     = sid >> 5;   // 0..63
    const int chunk = sid & 31;   // 0..31 (64 rows each)
    const int bt    = b >> 2;

    const float4* tb4 = reinterpret_cast<const float4*>(
        key + ((size_t)b * TDIM + chunk * 64) * KDIM);

    // ---- 1) prefetch rows {w*8+0, w*8+1 : w in 0..7} of own tile into smem
    //         (fills DRAM during mids duty / spin) ----
    const uint32_t ks_base = (uint32_t)__cvta_generic_to_shared(sh + SH_TILE);
#pragma unroll
    for (int r = 0; r < (PRE_ROWS * KDIM / 4) / 256; r++) {
        const int idx = tid + 256 * r;        // 0..2047 float4 slots
        const int s   = idx >> 7;             // smem row slot 0..15
        const int c   = idx & 127;            // float4 column
        const int g   = ((s >> 1) << 3) + (s & 1);  // tile row
        cp16(ks_base + (uint32_t)idx * 16, tb4 + g * 128 + c);
    }
    asm volatile("cp.async.commit_group;" ::: "memory");

    // ---- 2) mids duty (blocks 0..255 only; all wave-1 resident) ----
    if (sid < MIDS_DUTIES) {
        const int dkt = sid & 15;   // 0..15 (32 k each)
        const int dbt = sid >> 4;   // 0..15 (4 b each)

        float (*q_s)[QDIM] = reinterpret_cast<float(*)[QDIM]>(sh + SH_QS);
        {
            const float4* qg = reinterpret_cast<const float4*>(
                query + (size_t)dbt * 4 * QDIM);
            float4* qs4 = reinterpret_cast<float4*>(sh + SH_QS);
            qs4[tid]       = qg[tid];
            qs4[tid + 256] = qg[tid + 256];
        }
        __syncthreads();

#pragma unroll
        for (int pair = 0; pair < 2; pair++) {
            const int k0 = dkt * 32 + warp * 4 + pair * 2;
            const float4* w4a = reinterpret_cast<const float4*>(
                W + (size_t)k0 * QDIM);
            const float4* w4b = w4a + QDIM / 4;

            float a[2][4] = {};
#pragma unroll
            for (int j = 0; j < 4; j++) {
                const int idx = lane + 32 * j;
                const float4 w0 = w4a[idx];
                const float4 w1 = w4b[idx];
#pragma unroll
                for (int bb = 0; bb < 4; bb++) {
                    const float4 v = reinterpret_cast<const float4*>(q_s[bb])[idx];
                    a[0][bb] += w0.x * v.x + w0.y * v.y + w0.z * v.z + w0.w * v.w;
                    a[1][bb] += w1.x * v.x + w1.y * v.y + w1.z * v.z + w1.w * v.w;
                }
            }
#pragma unroll
            for (int o = 16; o; o >>= 1) {
#pragma unroll
                for (int bb = 0; bb < 4; bb++) {
                    a[0][bb] += __shfl_xor_sync(0xffffffffu, a[0][bb], o);
                    a[1][bb] += __shfl_xor_sync(0xffffffffu, a[1][bb], o);
                }
            }
            if (lane == 0) {
#pragma unroll
                for (int bb = 0; bb < 4; bb++) {
                    const int db = dbt * 4 + bb;
                    g_mids[(size_t)db * KDIM + k0]     = a[0][bb];
                    g_mids[(size_t)db * KDIM + k0 + 1] = a[1][bb];
                }
            }
        }
        __syncthreads();                      // q_s reads done before reuse
        if (tid == 0) red_release_add(&g_mids_cnt[dbt], 1);   // publish
    }

    // ---- 3) wait for this batch's mids ----
    if (tid == 0) {
        blockSum = 0.0f;
        spin_acquire(g_mids_cnt + bt, 16);
        int p = atomicAdd(&g_mids_passed[bt], 1);
        if (p == 127) { g_mids_cnt[bt] = 0; g_mids_passed[bt] = 0; }
    }
    __syncthreads();

    if (tid < KDIM / 4) {
        reinterpret_cast<float4*>(sh + SH_MS)[tid] =
            reinterpret_cast<const float4*>(g_mids + (size_t)b * KDIM)[tid];
    }
    asm volatile("cp.async.wait_group 0;" ::: "memory");
    __syncthreads();                          // ms + tile ready

    // ---- 4) scores hot loop (proven structure) ----
    float4 m[4];
#pragma unroll
    for (int j = 0; j < 4; j++)
        m[j] = reinterpret_cast<const float4*>(sh + SH_MS)[lane + 32 * j];

    const float4* ks4 = reinterpret_cast<const float4*>(sh + SH_TILE);
    const float4* s0  = ks4 + (warp * 2) * 128;      // row w*8+0
    const float4* s1  = s0 + 128;                    // row w*8+1
    const float4* kb  = tb4 + warp * 8 * 128;        // tile rows w*8..

    float a0 = 0.f, a1 = 0.f, a2 = 0.f, a3 = 0.f;
    float a4 = 0.f, a5 = 0.f, a6 = 0.f, a7 = 0.f;
#pragma unroll
    for (int j = 0; j < 4; j++) {
        const int idx = lane + 32 * j;
        const float4 mv = m[j];
        float4 v0 = s0[idx];                 // smem (prefetched)
        float4 v1 = s1[idx];                 // smem (prefetched)
        float4 v2 = __ldcs(kb + idx + 2 * 128);
        float4 v3 = __ldcs(kb + idx + 3 * 128);
        float4 v4 = __ldcs(kb + idx + 4 * 128);
        float4 v5 = __ldcs(kb + idx + 5 * 128);
        float4 v6 = __ldcs(kb + idx + 6 * 128);
        float4 v7 = __ldcs(kb + idx + 7 * 128);
        a0 += v0.x * mv.x + v0.y * mv.y + v0.z * mv.z + v0.w * mv.w;
        a1 += v1.x * mv.x + v1.y * mv.y + v1.z * mv.z + v1.w * mv.w;
        a2 += v2.x * mv.x + v2.y * mv.y + v2.z * mv.z + v2.w * mv.w;
        a3 += v3.x * mv.x + v3.y * mv.y + v3.z * mv.z + v3.w * mv.w;
        a4 += v4.x * mv.x + v4.y * mv.y + v4.z * mv.z + v4.w * mv.w;
        a5 += v5.x * mv.x + v5.y * mv.y + v5.z * mv.z + v5.w * mv.w;
        a6 += v6.x * mv.x + v6.y * mv.y + v6.z * mv.z + v6.w * mv.w;
        a7 += v7.x * mv.x + v7.y * mv.y + v7.z * mv.z + v7.w * mv.w;
    }
#pragma unroll
    for (int o = 16; o; o >>= 1) {
        a0 += __shfl_xor_sync(0xffffffffu, a0, o);
        a1 += __shfl_xor_sync(0xffffffffu, a1, o);
        a2 += __shfl_xor_sync(0xffffffffu, a2, o);
        a3 += __shfl_xor_sync(0xffffffffu, a3, o);
        a4 += __shfl_xor_sync(0xffffffffu, a4, o);
        a5 += __shfl_xor_sync(0xffffffffu, a5, o);
        a6 += __shfl_xor_sync(0xffffffffu, a6, o);
        a7 += __shfl_xor_sync(0xffffffffu, a7, o);
    }

    if (lane == 0) {
        const float bv = bias[0];
        float4 e0, e1;
        e0.x = __expf(tanhf(a0 + bv));
        e0.y = __expf(tanhf(a1 + bv));
        e0.z = __expf(tanhf(a2 + bv));
        e0.w = __expf(tanhf(a3 + bv));
        e1.x = __expf(tanhf(a4 + bv));
        e1.y = __expf(tanhf(a5 + bv));
        e1.z = __expf(tanhf(a6 + bv));
        e1.w = __expf(tanhf(a7 + bv));
        const int ta = chunk * 64 + warp * 8;
        float4* op = reinterpret_cast<float4*>(out + (size_t)b * TDIM + ta);
        op[0] = e0;
        op[1] = e1;
        atomicAdd(&blockSum,
                  ((e0.x + e0.y) + (e0.z + e0.w)) +
                  ((e1.x + e1.y) + (e1.z + e1.w)));
    }
    __syncthreads();

    // ---- 5) epilogue: last block of each batch normalizes in place ----
    __shared__ int amLast;
    if (tid == 0) {
        atomicAdd(&g_sums[b], blockSum);
        // acq_rel: releases our out-stores+sum; acquires all others' if last
        amLast = (atom_acqrel_add(&g_sc_cnt[b], 1) == 31);
    }
    __syncthreads();

    if (amLast) {
        const float inv = 1.0f / __ldcg(&g_sums[b]);
        float4* o4 = reinterpret_cast<float4*>(out + (size_t)b * TDIM);
#pragma unroll
        for (int r = 0; r < 2; r++) {
            const int i = tid + r * 256;     // 512 float4 per batch
            float4 v = __ldcg(&o4[i]);
            v.x *= inv; v.y *= inv; v.z *= inv; v.w *= inv;
            o4[i] = v;
        }
        __syncthreads();
        if (tid == 0) {                      // reset for graph replay
            g_sc_cnt[b] = 0;
            g_sums[b]   = 0.0f;
        }
    }
}

// ---------------------------------------------------------------------------
// Inputs (metadata order): query [64,512], key [64,2048,512], W [512,512],
// bias [1]. Output: [64,2048] float32.
// ---------------------------------------------------------------------------
extern "C" void kernel_launch(void* const* d_in, const int* in_sizes, int n_in,
                              void* d_out, int out_size)
{
    const float* query = (const float*)d_in[0];
    const float* key   = (const float*)d_in[1];
    const float* W     = (const float*)d_in[2];
    const float* bias  = (const float*)d_in[3];
    float* out = (float*)d_out;

    fused_kernel<<<SCORE_BLOCKS, 256>>>(query, key, W, bias, out);
}